// round 2
// baseline (speedup 1.0000x reference)
#include <cuda_runtime.h>
#include <cuda_bf16.h>
#include <cstdint>

// ---------------- problem constants (from reference setup_inputs) ----------------
#define MAX_N 20000
#define MAX_E 320000
#define R_REL 5
#define IN_DIM 64
#define IN0 112          // 64 + 32 + 16
#define HID 256
#define NHEAD 4
#define HDIM 64
#define NEG_SLOPE 0.2f

// ---------------- static device scratch (no runtime allocation allowed) ----------
__device__ float g_h0[(size_t)MAX_N * IN0];
__device__ float g_agg[(size_t)MAX_N * IN_DIM];
__device__ float g_deg[MAX_N];
__device__ float g_xl[(size_t)R_REL * MAX_N * HID];   // 102.4 MB
__device__ float g_xr[(size_t)R_REL * MAX_N * HID];   // 102.4 MB
__device__ float g_ex[(size_t)R_REL * MAX_E * NHEAD]; // 25.6 MB
__device__ float g_denom[(size_t)R_REL * MAX_N * NHEAD];
__device__ float g_conv[(size_t)MAX_N * HID];
__device__ float g_h1[(size_t)MAX_N * HID];

// ---------------- helpers ----------------
__device__ __forceinline__ void red_add_v4(float* p, float a, float b, float c, float d) {
    asm volatile("red.global.add.v4.f32 [%0], {%1,%2,%3,%4};"
                 :: "l"(p), "f"(a), "f"(b), "f"(c), "f"(d) : "memory");
}
__device__ __forceinline__ void red_add_v2(float* p, float a, float b) {
    asm volatile("red.global.add.v2.f32 [%0], {%1,%2};"
                 :: "l"(p), "f"(a), "f"(b) : "memory");
}
__device__ __forceinline__ float lrelu(float m) { return m > 0.f ? m : NEG_SLOPE * m; }

// ---------------- kernels ----------------
__global__ void k_zero_pre(int N) {
    int i = blockIdx.x * blockDim.x + threadIdx.x;
    if (i < N * IN_DIM) g_agg[i] = 0.f;
    if (i < N) g_deg[i] = 0.f;
}

__global__ void k_zero_denom(int N) {
    int i = blockIdx.x * blockDim.x + threadIdx.x;
    if (i < N * R_REL * NHEAD) g_denom[i] = 0.f;
}

// mean-neighbor aggregation over the union of all relations (warp per edge)
__global__ void k_pearl_agg(const float* __restrict__ x, const int* __restrict__ ei,
                            int N, int E) {
    int w = (blockIdx.x * blockDim.x + threadIdx.x) >> 5;
    int lane = threadIdx.x & 31;
    if (w >= R_REL * E) return;
    int r = w / E, e = w - r * E;
    int src = ei[(size_t)(r * 2 + 0) * E + e];
    int dst = ei[(size_t)(r * 2 + 1) * E + e];
    float2 v = *(const float2*)(x + (size_t)src * IN_DIM + lane * 2);
    red_add_v2(g_agg + (size_t)dst * IN_DIM + lane * 2, v.x, v.y);
    if (lane == 0) atomicAdd(&g_deg[dst], 1.f);
}

// build h0 = [x | tanh(mean_agg @ Wp + bp) | time_pe]  (block per node)
__global__ void __launch_bounds__(128) k_build_h0(const float* __restrict__ x,
                                                  const int* __restrict__ date,
                                                  const float* __restrict__ Wp,
                                                  const float* __restrict__ bp, int N) {
    int n = blockIdx.x;
    int t = threadIdx.x;
    __shared__ float s_am[IN_DIM];
    float inv = 1.f / fmaxf(g_deg[n], 1.f);
    if (t < IN_DIM) s_am[t] = g_agg[(size_t)n * IN_DIM + t] * inv;
    __syncthreads();
    float* hrow = g_h0 + (size_t)n * IN0;
    if (t < 64) {
        hrow[t] = x[(size_t)n * IN_DIM + t];
    } else if (t < 96) {
        int c = t - 64;
        float acc = bp[c];
        #pragma unroll
        for (int k = 0; k < IN_DIM; k++) acc += s_am[k] * Wp[k * 32 + c];
        hrow[64 + c] = tanhf(acc);
    } else if (t < 112) {
        int j = t - 96;
        int jj = j & 7;
        float tt = (float)date[n] / 10000.f;
        float div = expf(-(float)(2 * jj) * (logf(10000.f) / 16.f));
        float a = tt * div;
        hrow[96 + j] = (j < 8) ? sinf(a) : cosf(a);
    }
}

// batched SGEMM: C[z] = A @ B[z];  z<5 -> (Wl, g_xl), z>=5 -> (Wr, g_xr)
// A = g_h0 (K=112) or g_h1 (K=256). 64x64 tile, 256 threads, 4x4 microtile.
__global__ void __launch_bounds__(256) k_gemm(const float* __restrict__ Wl,
                                              const float* __restrict__ Wr,
                                              int N, int K) {
    int z = blockIdx.z;
    const float* A = (K == IN0) ? g_h0 : g_h1;
    const float* B = (z < R_REL) ? Wl + (size_t)z * K * HID
                                 : Wr + (size_t)(z - R_REL) * K * HID;
    float* C = (z < R_REL) ? g_xl + (size_t)z * N * HID
                           : g_xr + (size_t)(z - R_REL) * N * HID;
    __shared__ float As[16][64];   // [kk][row]
    __shared__ float Bs[16][64];   // [kk][col]
    int tid = threadIdx.x;
    int row0 = blockIdx.y * 64, col0 = blockIdx.x * 64;
    int tx = tid & 15, ty = tid >> 4;
    float acc[4][4] = {};
    int ar = (tid * 4) >> 4, ac = (tid * 4) & 15;
    int br = (tid * 4) >> 6, bc = (tid * 4) & 63;
    for (int k0 = 0; k0 < K; k0 += 16) {
        float4 av = make_float4(0.f, 0.f, 0.f, 0.f);
        int gr = row0 + ar;
        if (gr < N) av = *(const float4*)(A + (size_t)gr * K + k0 + ac);
        As[ac + 0][ar] = av.x; As[ac + 1][ar] = av.y;
        As[ac + 2][ar] = av.z; As[ac + 3][ar] = av.w;
        *(float4*)&Bs[br][bc] = *(const float4*)(B + (size_t)(k0 + br) * HID + col0 + bc);
        __syncthreads();
        #pragma unroll
        for (int kk = 0; kk < 16; kk++) {
            float a[4], b[4];
            #pragma unroll
            for (int i = 0; i < 4; i++) a[i] = As[kk][ty * 4 + i];
            #pragma unroll
            for (int j = 0; j < 4; j++) b[j] = Bs[kk][tx * 4 + j];
            #pragma unroll
            for (int i = 0; i < 4; i++)
                #pragma unroll
                for (int j = 0; j < 4; j++) acc[i][j] += a[i] * b[j];
        }
        __syncthreads();
    }
    #pragma unroll
    for (int i = 0; i < 4; i++) {
        int gr = row0 + ty * 4 + i;
        if (gr < N) {
            float4 v = make_float4(acc[i][0], acc[i][1], acc[i][2], acc[i][3]);
            *(float4*)(C + (size_t)gr * HID + col0 + tx * 4) = v;
        }
    }
}

// conv init: conv[n][c] = sum_r b[r][c]
__global__ void k_conv_init(const float* __restrict__ b, int N) {
    int i = blockIdx.x * blockDim.x + threadIdx.x;
    if (i >= N * HID) return;
    int c = i & (HID - 1);
    float s = 0.f;
    #pragma unroll
    for (int r = 0; r < R_REL; r++) s += b[r * HID + c];
    g_conv[i] = s;
}

// edge pass 1: e -> exp(e), atomic denom  (warp per edge, relation = arg)
__global__ void __launch_bounds__(256) k_edge1(const int* __restrict__ ei,
                                               const float* __restrict__ att,
                                               int r, int N, int E) {
    int w = (blockIdx.x * blockDim.x + threadIdx.x) >> 5;
    int lane = threadIdx.x & 31;
    if (w >= E) return;
    int src = ei[(size_t)(r * 2 + 0) * E + w];
    int dst = ei[(size_t)(r * 2 + 1) * E + w];
    const float4* xl = (const float4*)(g_xl + ((size_t)r * N + src) * HID + lane * 8);
    const float4* xr = (const float4*)(g_xr + ((size_t)r * N + dst) * HID + lane * 8);
    const float4* at = (const float4*)(att + r * HID + lane * 8);
    float4 l0 = xl[0], l1 = xl[1];
    float4 r0 = xr[0], r1 = xr[1];
    float4 a0 = at[0], a1 = at[1];
    float s = lrelu(l0.x + r0.x) * a0.x + lrelu(l0.y + r0.y) * a0.y
            + lrelu(l0.z + r0.z) * a0.z + lrelu(l0.w + r0.w) * a0.w
            + lrelu(l1.x + r1.x) * a1.x + lrelu(l1.y + r1.y) * a1.y
            + lrelu(l1.z + r1.z) * a1.z + lrelu(l1.w + r1.w) * a1.w;
    // reduce over the 8-lane group that shares a head
    s += __shfl_xor_sync(0xffffffffu, s, 4);
    s += __shfl_xor_sync(0xffffffffu, s, 2);
    s += __shfl_xor_sync(0xffffffffu, s, 1);
    if ((lane & 7) == 0) {
        int h = lane >> 3;
        float ex = expf(s);
        g_ex[((size_t)r * E + w) * NHEAD + h] = ex;
        atomicAdd(&g_denom[((size_t)r * N + dst) * NHEAD + h], ex);
    }
}

// edge pass 2: conv[dst] += alpha * xl[src]   (vector reductions)
__global__ void __launch_bounds__(256) k_edge2(const int* __restrict__ ei,
                                               int r, int N, int E) {
    int w = (blockIdx.x * blockDim.x + threadIdx.x) >> 5;
    int lane = threadIdx.x & 31;
    if (w >= E) return;
    int src = ei[(size_t)(r * 2 + 0) * E + w];
    int dst = ei[(size_t)(r * 2 + 1) * E + w];
    int h = lane >> 3;
    float ex = g_ex[((size_t)r * E + w) * NHEAD + h];
    float den = g_denom[((size_t)r * N + dst) * NHEAD + h];
    float alpha = ex / (den + 1e-16f);
    const float4* xl = (const float4*)(g_xl + ((size_t)r * N + src) * HID + lane * 8);
    float4 l0 = xl[0], l1 = xl[1];
    float* op = g_conv + (size_t)dst * HID + lane * 8;
    red_add_v4(op, alpha * l0.x, alpha * l0.y, alpha * l0.z, alpha * l0.w);
    red_add_v4(op + 4, alpha * l1.x, alpha * l1.y, alpha * l1.z, alpha * l1.w);
}

__global__ void k_relu(int N) {
    int i = blockIdx.x * blockDim.x + threadIdx.x;
    if (i < N * HID) g_h1[i] = fmaxf(g_conv[i], 0.f);
}

// output MLP: relu(h @ W1 + b1) @ W2 + b2, 4 nodes per block
__global__ void __launch_bounds__(128) k_mlp(const float* __restrict__ W1,
                                             const float* __restrict__ b1,
                                             const float* __restrict__ W2,
                                             const float* __restrict__ b2,
                                             float* __restrict__ out, int N) {
    int n0 = blockIdx.x * 4;
    int t = threadIdx.x;
    __shared__ float sh[4][HID];
    __shared__ float so[4][128];
    for (int i = t; i < 4 * HID; i += 128) {
        int u = i >> 8, c = i & (HID - 1);
        int n = n0 + u;
        sh[u][c] = (n < N) ? g_h1[(size_t)n * HID + c] : 0.f;
    }
    __syncthreads();
    float acc[4] = {b1[t], b1[t], b1[t], b1[t]};
    #pragma unroll 4
    for (int k = 0; k < HID; k++) {
        float wv = W1[k * 128 + t];
        #pragma unroll
        for (int u = 0; u < 4; u++) acc[u] += sh[u][k] * wv;
    }
    #pragma unroll
    for (int u = 0; u < 4; u++) so[u][t] = fmaxf(acc[u], 0.f);
    __syncthreads();
    if (t < 12) {
        int u = t / 3, j = t - u * 3;
        int n = n0 + u;
        if (n < N) {
            float a = b2[j];
            #pragma unroll 4
            for (int k = 0; k < 128; k++) a += so[u][k] * W2[k * 3 + j];
            out[(size_t)n * 3 + j] = a;
        }
    }
}

// ---------------- launch ----------------
extern "C" void kernel_launch(void* const* d_in, const int* in_sizes, int n_in,
                              void* d_out, int out_size) {
    const float* x     = (const float*)d_in[0];
    const int*   date  = (const int*)d_in[1];
    const int*   ei    = (const int*)d_in[2];
    const float* pW    = (const float*)d_in[3];
    const float* pb    = (const float*)d_in[4];
    const float* Wl0   = (const float*)d_in[5];
    const float* Wr0   = (const float*)d_in[6];
    const float* att0  = (const float*)d_in[7];
    const float* b0    = (const float*)d_in[8];
    const float* Wl1   = (const float*)d_in[9];
    const float* Wr1   = (const float*)d_in[10];
    const float* att1  = (const float*)d_in[11];
    const float* b1    = (const float*)d_in[12];
    // d_in[13..15] = aggW/aggb/agga: provably unused (rel_agg over identical copies == identity)
    const float* oW1   = (const float*)d_in[16];
    const float* ob1   = (const float*)d_in[17];
    const float* oW2   = (const float*)d_in[18];
    const float* ob2   = (const float*)d_in[19];
    float* out = (float*)d_out;

    int N = in_sizes[0] / IN_DIM;
    int E = in_sizes[2] / (R_REL * 2);

    // ---- PE features + h0 ----
    k_zero_pre<<<(N * IN_DIM + 255) / 256, 256>>>(N);
    k_pearl_agg<<<(R_REL * E + 7) / 8, 256>>>(x, ei, N, E);
    k_build_h0<<<N, 128>>>(x, date, pW, pb, N);

    dim3 gemm_grid(HID / 64, (N + 63) / 64, 2 * R_REL);
    dim3 edge_grid((E + 7) / 8, 1, 1);

    // ---- GNN layer 0 ----
    k_gemm<<<gemm_grid, 256>>>(Wl0, Wr0, N, IN0);
    k_zero_denom<<<(N * R_REL * NHEAD + 255) / 256, 256>>>(N);
    k_conv_init<<<(N * HID + 255) / 256, 256>>>(b0, N);
    for (int r = 0; r < R_REL; r++) {       // serialize relations: keep xl[r]/xr[r] hot in L2
        k_edge1<<<edge_grid, 256>>>(ei, att0, r, N, E);
        k_edge2<<<edge_grid, 256>>>(ei, r, N, E);
    }
    k_relu<<<(N * HID + 255) / 256, 256>>>(N);

    // ---- GNN layer 1 ----
    k_gemm<<<gemm_grid, 256>>>(Wl1, Wr1, N, HID);
    k_zero_denom<<<(N * R_REL * NHEAD + 255) / 256, 256>>>(N);
    k_conv_init<<<(N * HID + 255) / 256, 256>>>(b1, N);
    for (int r = 0; r < R_REL; r++) {
        k_edge1<<<edge_grid, 256>>>(ei, att1, r, N, E);
        k_edge2<<<edge_grid, 256>>>(ei, r, N, E);
    }
    k_relu<<<(N * HID + 255) / 256, 256>>>(N);

    // ---- output MLP ----
    k_mlp<<<(N + 3) / 4, 128>>>(oW1, ob1, oW2, ob2, out, N);
}

// round 3
// speedup vs baseline: 1.8416x; 1.8416x over previous
#include <cuda_runtime.h>
#include <cuda_bf16.h>
#include <cstdint>

// ---------------- problem constants ----------------
#define MAX_N 20000
#define MAX_E 320000
#define R_REL 5
#define IN_DIM 64
#define IN0 112          // 64 + 32 + 16
#define HID 256
#define NHEAD 4
#define NEG_SLOPE 0.2f

// ---------------- static device scratch ----------
__device__ float g_h0[(size_t)MAX_N * IN0];
__device__ float g_agg[(size_t)MAX_N * IN_DIM];
__device__ float g_xl[(size_t)R_REL * MAX_N * HID];
__device__ float g_xr[(size_t)R_REL * MAX_N * HID];
__device__ float g_conv[(size_t)MAX_N * HID];
__device__ float g_h1[(size_t)MAX_N * HID];
// CSR scratch
__device__ int g_cnt[R_REL * MAX_N];
__device__ int g_cur[R_REL * MAX_N];
__device__ int g_off[R_REL * MAX_N];
__device__ int g_csr[(size_t)R_REL * MAX_E];

__device__ __forceinline__ float lrelu(float m) { return m > 0.f ? m : NEG_SLOPE * m; }

// ---------------- CSR build ----------------
__global__ void k_zero_cc(int N) {
    int i = blockIdx.x * blockDim.x + threadIdx.x;
    if (i < R_REL * N) { g_cnt[i] = 0; g_cur[i] = 0; }
}

__global__ void k_hist(const int* __restrict__ ei, int N, int E) {
    int i = blockIdx.x * blockDim.x + threadIdx.x;
    if (i >= R_REL * E) return;
    int r = i / E, e = i - r * E;
    int dst = ei[(size_t)(r * 2 + 1) * E + e];
    atomicAdd(&g_cnt[r * N + dst], 1);
}

// exclusive scan per relation (one 1024-thread block per relation)
__global__ void __launch_bounds__(1024) k_scan(int N) {
    int r = blockIdx.x;
    __shared__ int sh[1024];
    int t = threadIdx.x;
    int carry = 0;
    int nchunk = (N + 1023) / 1024;
    for (int c = 0; c < nchunk; c++) {
        int i = c * 1024 + t;
        int v = (i < N) ? g_cnt[r * N + i] : 0;
        sh[t] = v;
        __syncthreads();
        #pragma unroll
        for (int off = 1; off < 1024; off <<= 1) {
            int x = (t >= off) ? sh[t - off] : 0;
            __syncthreads();
            if (t >= off) sh[t] += x;
            __syncthreads();
        }
        int incl = sh[t];
        if (i < N) g_off[r * N + i] = incl - v + carry;
        carry += sh[1023];
        __syncthreads();
    }
}

__global__ void k_scatter(const int* __restrict__ ei, int N, int E) {
    int i = blockIdx.x * blockDim.x + threadIdx.x;
    if (i >= R_REL * E) return;
    int r = i / E, e = i - r * E;
    int src = ei[(size_t)(r * 2 + 0) * E + e];
    int dst = ei[(size_t)(r * 2 + 1) * E + e];
    int pos = g_off[r * N + dst] + atomicAdd(&g_cur[r * N + dst], 1);
    g_csr[(size_t)r * E + pos] = src;
}

// ---------------- PEARL mean aggregation (warp per dst, CSR) ----------------
__global__ void __launch_bounds__(256) k_pearl(const float* __restrict__ x, int N, int E) {
    int w = (blockIdx.x * blockDim.x + threadIdx.x) >> 5;
    int lane = threadIdx.x & 31;
    if (w >= N) return;
    int d = w;
    float ax = 0.f, ay = 0.f;
    int deg = 0;
    #pragma unroll
    for (int r = 0; r < R_REL; r++) {
        int beg = g_off[r * N + d], num = g_cnt[r * N + d];
        deg += num;
        const int* srcs = g_csr + (size_t)r * E + beg;
        for (int base = 0; base < num; base += 32) {
            int my = (base + lane < num) ? srcs[base + lane] : 0;
            int lim = min(32, num - base);
            for (int q = 0; q < lim; q++) {
                int src = __shfl_sync(0xffffffffu, my, q);
                float2 v = *(const float2*)(x + (size_t)src * IN_DIM + lane * 2);
                ax += v.x; ay += v.y;
            }
        }
    }
    float inv = 1.f / fmaxf((float)deg, 1.f);
    *(float2*)(g_agg + (size_t)d * IN_DIM + lane * 2) = make_float2(ax * inv, ay * inv);
}

// build h0 = [x | tanh(mean_agg @ Wp + bp) | time_pe]
__global__ void __launch_bounds__(128) k_build_h0(const float* __restrict__ x,
                                                  const int* __restrict__ date,
                                                  const float* __restrict__ Wp,
                                                  const float* __restrict__ bp, int N) {
    int n = blockIdx.x;
    int t = threadIdx.x;
    __shared__ float s_am[IN_DIM];
    if (t < IN_DIM) s_am[t] = g_agg[(size_t)n * IN_DIM + t];
    __syncthreads();
    float* hrow = g_h0 + (size_t)n * IN0;
    if (t < 64) {
        hrow[t] = x[(size_t)n * IN_DIM + t];
    } else if (t < 96) {
        int c = t - 64;
        float acc = bp[c];
        #pragma unroll
        for (int k = 0; k < IN_DIM; k++) acc += s_am[k] * Wp[k * 32 + c];
        hrow[64 + c] = tanhf(acc);
    } else if (t < 112) {
        int j = t - 96;
        int jj = j & 7;
        float tt = (float)date[n] / 10000.f;
        float div = expf(-(float)(2 * jj) * (logf(10000.f) / 16.f));
        float a = tt * div;
        hrow[96 + j] = (j < 8) ? sinf(a) : cosf(a);
    }
}

// batched SGEMM: 128x128 tile, 256 threads, 8x8 microtile (4 FMA per LDS-float)
__global__ void __launch_bounds__(256) k_gemm(const float* __restrict__ Wl,
                                              const float* __restrict__ Wr,
                                              int N, int K) {
    int z = blockIdx.z;
    const float* A = (K == IN0) ? g_h0 : g_h1;
    const float* B = (z < R_REL) ? Wl + (size_t)z * K * HID
                                 : Wr + (size_t)(z - R_REL) * K * HID;
    float* C = (z < R_REL) ? g_xl + (size_t)z * N * HID
                           : g_xr + (size_t)(z - R_REL) * N * HID;
    __shared__ float As[16][132];   // [kk][row], padded for aligned LDS.128
    __shared__ float Bs[16][128];   // [kk][col]
    int tid = threadIdx.x;
    int row0 = blockIdx.y * 128, col0 = blockIdx.x * 128;
    int tx = tid & 15, ty = tid >> 4;
    float acc[8][8] = {};
    for (int k0 = 0; k0 < K; k0 += 16) {
        #pragma unroll
        for (int i = 0; i < 2; i++) {
            int idx = tid * 2 + i;              // 0..511
            int ar = idx >> 2, ac4 = (idx & 3) * 4;
            float4 av = make_float4(0.f, 0.f, 0.f, 0.f);
            int gr = row0 + ar;
            if (gr < N) av = *(const float4*)(A + (size_t)gr * K + k0 + ac4);
            As[ac4 + 0][ar] = av.x; As[ac4 + 1][ar] = av.y;
            As[ac4 + 2][ar] = av.z; As[ac4 + 3][ar] = av.w;
            int br = idx >> 5, bc = (idx & 31) * 4;
            *(float4*)&Bs[br][bc] = *(const float4*)(B + (size_t)(k0 + br) * HID + col0 + bc);
        }
        __syncthreads();
        #pragma unroll
        for (int kk = 0; kk < 16; kk++) {
            float a[8], b[8];
            *(float4*)(a)     = *(const float4*)&As[kk][ty * 8];
            *(float4*)(a + 4) = *(const float4*)&As[kk][ty * 8 + 4];
            *(float4*)(b)     = *(const float4*)&Bs[kk][tx * 8];
            *(float4*)(b + 4) = *(const float4*)&Bs[kk][tx * 8 + 4];
            #pragma unroll
            for (int i = 0; i < 8; i++)
                #pragma unroll
                for (int j = 0; j < 8; j++) acc[i][j] += a[i] * b[j];
        }
        __syncthreads();
    }
    #pragma unroll
    for (int i = 0; i < 8; i++) {
        int gr = row0 + ty * 8 + i;
        if (gr < N) {
            *(float4*)(C + (size_t)gr * HID + col0 + tx * 8) =
                make_float4(acc[i][0], acc[i][1], acc[i][2], acc[i][3]);
            *(float4*)(C + (size_t)gr * HID + col0 + tx * 8 + 4) =
                make_float4(acc[i][4], acc[i][5], acc[i][6], acc[i][7]);
        }
    }
}

// conv init: conv[n][c] = sum_r b[r][c]
__global__ void k_conv_init(const float* __restrict__ b, int N) {
    int i = blockIdx.x * blockDim.x + threadIdx.x;
    if (i >= N * HID) return;
    int c = i & (HID - 1);
    float s = 0.f;
    #pragma unroll
    for (int r = 0; r < R_REL; r++) s += b[r * HID + c];
    g_conv[i] = s;
}

// GATv2 aggregation: warp per dst node, single pass over in-edges (CSR).
// out[dst] = (sum_e exp(e)*xl[src_e]) / (sum_e exp(e))   [per head]
__global__ void __launch_bounds__(256) k_gat(const float* __restrict__ att,
                                             int r, int N, int E, int last) {
    int w = (blockIdx.x * blockDim.x + threadIdx.x) >> 5;
    int lane = threadIdx.x & 31;
    if (w >= N) return;
    int d = w;
    int beg = g_off[r * N + d], num = g_cnt[r * N + d];
    const float* xlbase = g_xl + (size_t)r * N * HID;
    const float4* xr4 = (const float4*)(g_xr + ((size_t)r * N + d) * HID + lane * 8);
    float4 r0 = xr4[0], r1 = xr4[1];
    const float4* at4 = (const float4*)(att + r * HID + lane * 8);
    float4 a0 = at4[0], a1 = at4[1];
    float acc0 = 0.f, acc1 = 0.f, acc2 = 0.f, acc3 = 0.f;
    float acc4 = 0.f, acc5 = 0.f, acc6 = 0.f, acc7 = 0.f;
    float denom = 0.f;
    const int* srcs = g_csr + (size_t)r * E + beg;
    for (int base = 0; base < num; base += 32) {
        int my = (base + lane < num) ? srcs[base + lane] : 0;
        int lim = min(32, num - base);
        for (int q = 0; q < lim; q++) {
            int src = __shfl_sync(0xffffffffu, my, q);
            const float4* xl = (const float4*)(xlbase + (size_t)src * HID + lane * 8);
            float4 l0 = xl[0], l1 = xl[1];
            float s = lrelu(l0.x + r0.x) * a0.x + lrelu(l0.y + r0.y) * a0.y
                    + lrelu(l0.z + r0.z) * a0.z + lrelu(l0.w + r0.w) * a0.w
                    + lrelu(l1.x + r1.x) * a1.x + lrelu(l1.y + r1.y) * a1.y
                    + lrelu(l1.z + r1.z) * a1.z + lrelu(l1.w + r1.w) * a1.w;
            // reduce over the 8-lane group sharing this head
            s += __shfl_xor_sync(0xffffffffu, s, 4);
            s += __shfl_xor_sync(0xffffffffu, s, 2);
            s += __shfl_xor_sync(0xffffffffu, s, 1);
            float ex = expf(s);
            denom += ex;
            acc0 += ex * l0.x; acc1 += ex * l0.y; acc2 += ex * l0.z; acc3 += ex * l0.w;
            acc4 += ex * l1.x; acc5 += ex * l1.y; acc6 += ex * l1.z; acc7 += ex * l1.w;
        }
    }
    float inv = 1.f / (denom + 1e-16f);
    float* cp = g_conv + (size_t)d * HID + lane * 8;
    float4 c0 = *(float4*)cp, c1 = *(float4*)(cp + 4);
    c0.x += acc0 * inv; c0.y += acc1 * inv; c0.z += acc2 * inv; c0.w += acc3 * inv;
    c1.x += acc4 * inv; c1.y += acc5 * inv; c1.z += acc6 * inv; c1.w += acc7 * inv;
    if (last) {
        float* hp = g_h1 + (size_t)d * HID + lane * 8;
        c0.x = fmaxf(c0.x, 0.f); c0.y = fmaxf(c0.y, 0.f);
        c0.z = fmaxf(c0.z, 0.f); c0.w = fmaxf(c0.w, 0.f);
        c1.x = fmaxf(c1.x, 0.f); c1.y = fmaxf(c1.y, 0.f);
        c1.z = fmaxf(c1.z, 0.f); c1.w = fmaxf(c1.w, 0.f);
        *(float4*)hp = c0; *(float4*)(hp + 4) = c1;
    } else {
        *(float4*)cp = c0; *(float4*)(cp + 4) = c1;
    }
}

// output MLP: relu(h @ W1 + b1) @ W2 + b2, 4 nodes per block
__global__ void __launch_bounds__(128) k_mlp(const float* __restrict__ W1,
                                             const float* __restrict__ b1,
                                             const float* __restrict__ W2,
                                             const float* __restrict__ b2,
                                             float* __restrict__ out, int N) {
    int n0 = blockIdx.x * 4;
    int t = threadIdx.x;
    __shared__ float sh[4][HID];
    __shared__ float so[4][128];
    for (int i = t; i < 4 * HID; i += 128) {
        int u = i >> 8, c = i & (HID - 1);
        int n = n0 + u;
        sh[u][c] = (n < N) ? g_h1[(size_t)n * HID + c] : 0.f;
    }
    __syncthreads();
    float acc[4] = {b1[t], b1[t], b1[t], b1[t]};
    #pragma unroll 4
    for (int k = 0; k < HID; k++) {
        float wv = W1[k * 128 + t];
        #pragma unroll
        for (int u = 0; u < 4; u++) acc[u] += sh[u][k] * wv;
    }
    #pragma unroll
    for (int u = 0; u < 4; u++) so[u][t] = fmaxf(acc[u], 0.f);
    __syncthreads();
    if (t < 12) {
        int u = t / 3, j = t - u * 3;
        int n = n0 + u;
        if (n < N) {
            float a = b2[j];
            #pragma unroll 4
            for (int k = 0; k < 128; k++) a += so[u][k] * W2[k * 3 + j];
            out[(size_t)n * 3 + j] = a;
        }
    }
}

// ---------------- launch ----------------
extern "C" void kernel_launch(void* const* d_in, const int* in_sizes, int n_in,
                              void* d_out, int out_size) {
    const float* x     = (const float*)d_in[0];
    const int*   date  = (const int*)d_in[1];
    const int*   ei    = (const int*)d_in[2];
    const float* pW    = (const float*)d_in[3];
    const float* pb    = (const float*)d_in[4];
    const float* Wl0   = (const float*)d_in[5];
    const float* Wr0   = (const float*)d_in[6];
    const float* att0  = (const float*)d_in[7];
    const float* b0    = (const float*)d_in[8];
    const float* Wl1   = (const float*)d_in[9];
    const float* Wr1   = (const float*)d_in[10];
    const float* att1  = (const float*)d_in[11];
    const float* b1    = (const float*)d_in[12];
    // d_in[13..15] = aggW/aggb/agga: dead (rel_agg over identical copies == identity)
    const float* oW1   = (const float*)d_in[16];
    const float* ob1   = (const float*)d_in[17];
    const float* oW2   = (const float*)d_in[18];
    const float* ob2   = (const float*)d_in[19];
    float* out = (float*)d_out;

    int N = in_sizes[0] / IN_DIM;
    int E = in_sizes[2] / (R_REL * 2);

    // ---- CSR build (shared by pearl + both layers) ----
    k_zero_cc<<<(R_REL * N + 255) / 256, 256>>>(N);
    k_hist<<<(R_REL * E + 255) / 256, 256>>>(ei, N, E);
    k_scan<<<R_REL, 1024>>>(N);
    k_scatter<<<(R_REL * E + 255) / 256, 256>>>(ei, N, E);

    // ---- PE features + h0 ----
    k_pearl<<<(N * 32 + 255) / 256, 256>>>(x, N, E);
    k_build_h0<<<N, 128>>>(x, date, pW, pb, N);

    dim3 gemm_grid((HID + 127) / 128, (N + 127) / 128, 2 * R_REL);
    int gat_grid = (N * 32 + 255) / 256;

    // ---- GNN layer 0 ----
    k_gemm<<<gemm_grid, 256>>>(Wl0, Wr0, N, IN0);
    k_conv_init<<<(N * HID + 255) / 256, 256>>>(b0, N);
    for (int r = 0; r < R_REL; r++)   // serialize relations: xl[r]/xr[r] stay hot in L2
        k_gat<<<gat_grid, 256>>>(att0, r, N, E, r == R_REL - 1);

    // ---- GNN layer 1 ----
    k_gemm<<<gemm_grid, 256>>>(Wl1, Wr1, N, HID);
    k_conv_init<<<(N * HID + 255) / 256, 256>>>(b1, N);
    for (int r = 0; r < R_REL; r++)
        k_gat<<<gat_grid, 256>>>(att1, r, N, E, r == R_REL - 1);

    // ---- output MLP ----
    k_mlp<<<(N + 3) / 4, 128>>>(oW1, ob1, oW2, ob2, out, N);
}

// round 5
// speedup vs baseline: 1.8479x; 1.0034x over previous
#include <cuda_runtime.h>
#include <cuda_bf16.h>
#include <cstdint>

// ---------------- problem constants ----------------
#define MAX_N 20000
#define MAX_E 320000
#define R_REL 5
#define IN_DIM 64
#define IN0 112          // 64 + 32 + 16
#define HID 256
#define NHEAD 4
#define NEG_SLOPE 0.2f

// ---------------- static device scratch ----------
__device__ float g_h0[(size_t)MAX_N * IN0];
__device__ float g_agg[(size_t)MAX_N * IN_DIM];
__device__ float g_xl[(size_t)R_REL * MAX_N * HID];
__device__ float g_xr[(size_t)R_REL * MAX_N * HID];
__device__ float g_conv[(size_t)MAX_N * HID];
__device__ float g_h1[(size_t)MAX_N * HID];
__device__ float g_bsum[2][HID];
// CSR scratch
__device__ int g_cnt[R_REL * MAX_N];
__device__ int g_cur[R_REL * MAX_N];
__device__ int g_off[R_REL * MAX_N];
__device__ int g_csr[(size_t)R_REL * MAX_E];

__device__ __forceinline__ float lrelu(float m) { return m > 0.f ? m : NEG_SLOPE * m; }

// ---------------- CSR build ----------------
__global__ void k_zero_cnt(int N) {
    int i = blockIdx.x * blockDim.x + threadIdx.x;
    if (i < R_REL * N) g_cnt[i] = 0;
}

__global__ void k_hist(const int* __restrict__ ei, int N, int E) {
    int i = blockIdx.x * blockDim.x + threadIdx.x;
    if (i >= R_REL * E) return;
    int r = i / E, e = i - r * E;
    int dst = ei[(size_t)(r * 2 + 1) * E + e];
    atomicAdd(&g_cnt[r * N + dst], 1);
}

// exclusive scan per relation (one 1024-thread block per relation)
__global__ void __launch_bounds__(1024) k_scan(int N) {
    int r = blockIdx.x;
    __shared__ int sh[1024];
    int t = threadIdx.x;
    int carry = 0;
    int nchunk = (N + 1023) / 1024;
    for (int c = 0; c < nchunk; c++) {
        int i = c * 1024 + t;
        int v = (i < N) ? g_cnt[r * N + i] : 0;
        sh[t] = v;
        __syncthreads();
        #pragma unroll
        for (int off = 1; off < 1024; off <<= 1) {
            int x = (t >= off) ? sh[t - off] : 0;
            __syncthreads();
            if (t >= off) sh[t] += x;
            __syncthreads();
        }
        int incl = sh[t];
        if (i < N) {
            int excl = incl - v + carry;
            g_off[r * N + i] = excl;
            g_cur[r * N + i] = excl;   // running cursor for scatter
        }
        carry += sh[1023];
        __syncthreads();
    }
}

__global__ void k_scatter(const int* __restrict__ ei, int N, int E) {
    int i = blockIdx.x * blockDim.x + threadIdx.x;
    if (i >= R_REL * E) return;
    int r = i / E, e = i - r * E;
    int src = ei[(size_t)(r * 2 + 0) * E + e];
    int dst = ei[(size_t)(r * 2 + 1) * E + e];
    int pos = atomicAdd(&g_cur[r * N + dst], 1);
    g_csr[(size_t)r * E + pos] = src;
}

// bias sums for both layers: g_bsum[l][c] = sum_r b_l[r][c]
__global__ void k_bsum(const float* __restrict__ b0, const float* __restrict__ b1) {
    int c = threadIdx.x;
    float s0 = 0.f, s1 = 0.f;
    #pragma unroll
    for (int r = 0; r < R_REL; r++) { s0 += b0[r * HID + c]; s1 += b1[r * HID + c]; }
    g_bsum[0][c] = s0; g_bsum[1][c] = s1;
}

// ---------------- PEARL mean aggregation (warp per dst, CSR) ----------------
__global__ void __launch_bounds__(256) k_pearl(const float* __restrict__ x, int N, int E) {
    int w = (blockIdx.x * blockDim.x + threadIdx.x) >> 5;
    int lane = threadIdx.x & 31;
    if (w >= N) return;
    int d = w;
    float ax = 0.f, ay = 0.f;
    int deg = 0;
    #pragma unroll
    for (int r = 0; r < R_REL; r++) {
        int beg = g_off[r * N + d], num = g_cnt[r * N + d];
        deg += num;
        const int* srcs = g_csr + (size_t)r * E + beg;
        for (int base = 0; base < num; base += 32) {
            int my = (base + lane < num) ? srcs[base + lane] : 0;
            int lim = min(32, num - base);
            for (int q = 0; q < lim; q++) {
                int src = __shfl_sync(0xffffffffu, my, q);
                float2 v = *(const float2*)(x + (size_t)src * IN_DIM + lane * 2);
                ax += v.x; ay += v.y;
            }
        }
    }
    float inv = 1.f / fmaxf((float)deg, 1.f);
    *(float2*)(g_agg + (size_t)d * IN_DIM + lane * 2) = make_float2(ax * inv, ay * inv);
}

// build h0 = [x | tanh(mean_agg @ Wp + bp) | time_pe]
__global__ void __launch_bounds__(128) k_build_h0(const float* __restrict__ x,
                                                  const int* __restrict__ date,
                                                  const float* __restrict__ Wp,
                                                  const float* __restrict__ bp, int N) {
    int n = blockIdx.x;
    int t = threadIdx.x;
    __shared__ float s_am[IN_DIM];
    if (t < IN_DIM) s_am[t] = g_agg[(size_t)n * IN_DIM + t];
    __syncthreads();
    float* hrow = g_h0 + (size_t)n * IN0;
    if (t < 64) {
        hrow[t] = x[(size_t)n * IN_DIM + t];
    } else if (t < 96) {
        int c = t - 64;
        float acc = bp[c];
        #pragma unroll
        for (int k = 0; k < IN_DIM; k++) acc += s_am[k] * Wp[k * 32 + c];
        hrow[64 + c] = tanhf(acc);
    } else if (t < 112) {
        int j = t - 96;
        int jj = j & 7;
        float tt = (float)date[n] / 10000.f;
        float div = expf(-(float)(2 * jj) * (logf(10000.f) / 16.f));
        float a = tt * div;
        hrow[96 + j] = (j < 8) ? sinf(a) : cosf(a);
    }
}

// batched SGEMM: 128x128 tile, 256 threads, 8x8 microtile
__global__ void __launch_bounds__(256) k_gemm(const float* __restrict__ Wl,
                                              const float* __restrict__ Wr,
                                              int N, int K) {
    int z = blockIdx.z;
    const float* A = (K == IN0) ? g_h0 : g_h1;
    const float* B = (z < R_REL) ? Wl + (size_t)z * K * HID
                                 : Wr + (size_t)(z - R_REL) * K * HID;
    float* C = (z < R_REL) ? g_xl + (size_t)z * N * HID
                           : g_xr + (size_t)(z - R_REL) * N * HID;
    __shared__ float As[16][132];
    __shared__ float Bs[16][128];
    int tid = threadIdx.x;
    int row0 = blockIdx.y * 128, col0 = blockIdx.x * 128;
    int tx = tid & 15, ty = tid >> 4;
    float acc[8][8] = {};
    for (int k0 = 0; k0 < K; k0 += 16) {
        #pragma unroll
        for (int i = 0; i < 2; i++) {
            int idx = tid * 2 + i;
            int ar = idx >> 2, ac4 = (idx & 3) * 4;
            float4 av = make_float4(0.f, 0.f, 0.f, 0.f);
            int gr = row0 + ar;
            if (gr < N) av = *(const float4*)(A + (size_t)gr * K + k0 + ac4);
            As[ac4 + 0][ar] = av.x; As[ac4 + 1][ar] = av.y;
            As[ac4 + 2][ar] = av.z; As[ac4 + 3][ar] = av.w;
            int br = idx >> 5, bc = (idx & 31) * 4;
            *(float4*)&Bs[br][bc] = *(const float4*)(B + (size_t)(k0 + br) * HID + col0 + bc);
        }
        __syncthreads();
        #pragma unroll
        for (int kk = 0; kk < 16; kk++) {
            float a[8], b[8];
            *(float4*)(a)     = *(const float4*)&As[kk][ty * 8];
            *(float4*)(a + 4) = *(const float4*)&As[kk][ty * 8 + 4];
            *(float4*)(b)     = *(const float4*)&Bs[kk][tx * 8];
            *(float4*)(b + 4) = *(const float4*)&Bs[kk][tx * 8 + 4];
            #pragma unroll
            for (int i = 0; i < 8; i++)
                #pragma unroll
                for (int j = 0; j < 8; j++) acc[i][j] += a[i] * b[j];
        }
        __syncthreads();
    }
    #pragma unroll
    for (int i = 0; i < 8; i++) {
        int gr = row0 + ty * 8 + i;
        if (gr < N) {
            *(float4*)(C + (size_t)gr * HID + col0 + tx * 8) =
                make_float4(acc[i][0], acc[i][1], acc[i][2], acc[i][3]);
            *(float4*)(C + (size_t)gr * HID + col0 + tx * 8 + 4) =
                make_float4(acc[i][4], acc[i][5], acc[i][6], acc[i][7]);
        }
    }
}

// raw (pre-reduce) attention score partial for this lane
__device__ __forceinline__ float raw_score(float4 l0, float4 l1, float4 r0, float4 r1,
                                           float4 a0, float4 a1) {
    return lrelu(l0.x + r0.x) * a0.x + lrelu(l0.y + r0.y) * a0.y
         + lrelu(l0.z + r0.z) * a0.z + lrelu(l0.w + r0.w) * a0.w
         + lrelu(l1.x + r1.x) * a1.x + lrelu(l1.y + r1.y) * a1.y
         + lrelu(l1.z + r1.z) * a1.z + lrelu(l1.w + r1.w) * a1.w;
}

// GATv2 aggregation: warp per dst, single pass, 2-wide software pipeline.
__global__ void __launch_bounds__(256) k_gat(const float* __restrict__ att,
                                             int r, int N, int E,
                                             int layer, int first, int last) {
    const unsigned F = 0xffffffffu;
    int w = (blockIdx.x * blockDim.x + threadIdx.x) >> 5;
    int lane = threadIdx.x & 31;
    if (w >= N) return;
    int d = w;
    int beg = g_off[r * N + d], num = g_cnt[r * N + d];
    const float* xlbase = g_xl + (size_t)r * N * HID;
    const float4* xr4 = (const float4*)(g_xr + ((size_t)r * N + d) * HID + lane * 8);
    float4 r0 = xr4[0], r1 = xr4[1];
    const float4* at4 = (const float4*)(att + r * HID + lane * 8);
    float4 a0 = at4[0], a1 = at4[1];
    float acc0 = 0.f, acc1 = 0.f, acc2 = 0.f, acc3 = 0.f;
    float acc4 = 0.f, acc5 = 0.f, acc6 = 0.f, acc7 = 0.f;
    float denom = 0.f;
    const int* srcs = g_csr + (size_t)r * E + beg;
    for (int base = 0; base < num; base += 32) {
        int lim = min(32, num - base);
        int my = srcs[base + ((base + lane < num) ? lane : 0)];
        // prefetch pair 0
        float4 p00, p01, p10, p11;
        {
            int s0 = __shfl_sync(F, my, 0);
            const float4* xp = (const float4*)(xlbase + (size_t)s0 * HID + lane * 8);
            p00 = xp[0]; p01 = xp[1];
        }
        if (lim > 1) {
            int s1 = __shfl_sync(F, my, 1);
            const float4* xp = (const float4*)(xlbase + (size_t)s1 * HID + lane * 8);
            p10 = xp[0]; p11 = xp[1];
        }
        for (int q = 0; q < lim; q += 2) {
            float4 c00 = p00, c01 = p01, c10 = p10, c11 = p11;
            int has2 = (q + 1 < lim);
            // prefetch pair q+2 / q+3 (issues before the shfl/exp chain below)
            if (q + 2 < lim) {
                int sn = __shfl_sync(F, my, q + 2);
                const float4* xp = (const float4*)(xlbase + (size_t)sn * HID + lane * 8);
                p00 = xp[0]; p01 = xp[1];
            }
            if (q + 3 < lim) {
                int sn = __shfl_sync(F, my, q + 3);
                const float4* xp = (const float4*)(xlbase + (size_t)sn * HID + lane * 8);
                p10 = xp[0]; p11 = xp[1];
            }
            float sA = raw_score(c00, c01, r0, r1, a0, a1);
            float sB = has2 ? raw_score(c10, c11, r0, r1, a0, a1) : 0.f;
            // interleaved 8-lane head reductions (uniform control: lim/q warp-uniform)
            sA += __shfl_xor_sync(F, sA, 4);  sB += __shfl_xor_sync(F, sB, 4);
            sA += __shfl_xor_sync(F, sA, 2);  sB += __shfl_xor_sync(F, sB, 2);
            sA += __shfl_xor_sync(F, sA, 1);  sB += __shfl_xor_sync(F, sB, 1);
            float exA = expf(sA);
            denom += exA;
            acc0 += exA * c00.x; acc1 += exA * c00.y; acc2 += exA * c00.z; acc3 += exA * c00.w;
            acc4 += exA * c01.x; acc5 += exA * c01.y; acc6 += exA * c01.z; acc7 += exA * c01.w;
            if (has2) {
                float exB = expf(sB);
                denom += exB;
                acc0 += exB * c10.x; acc1 += exB * c10.y; acc2 += exB * c10.z; acc3 += exB * c10.w;
                acc4 += exB * c11.x; acc5 += exB * c11.y; acc6 += exB * c11.z; acc7 += exB * c11.w;
            }
        }
    }
    float inv = 1.f / (denom + 1e-16f);
    float* cp = g_conv + (size_t)d * HID + lane * 8;
    float4 c0, c1;
    if (first) {
        c0 = *(const float4*)&g_bsum[layer][lane * 8];
        c1 = *(const float4*)&g_bsum[layer][lane * 8 + 4];
    } else {
        c0 = *(float4*)cp; c1 = *(float4*)(cp + 4);
    }
    c0.x += acc0 * inv; c0.y += acc1 * inv; c0.z += acc2 * inv; c0.w += acc3 * inv;
    c1.x += acc4 * inv; c1.y += acc5 * inv; c1.z += acc6 * inv; c1.w += acc7 * inv;
    if (last) {
        float* hp = g_h1 + (size_t)d * HID + lane * 8;
        c0.x = fmaxf(c0.x, 0.f); c0.y = fmaxf(c0.y, 0.f);
        c0.z = fmaxf(c0.z, 0.f); c0.w = fmaxf(c0.w, 0.f);
        c1.x = fmaxf(c1.x, 0.f); c1.y = fmaxf(c1.y, 0.f);
        c1.z = fmaxf(c1.z, 0.f); c1.w = fmaxf(c1.w, 0.f);
        *(float4*)hp = c0; *(float4*)(hp + 4) = c1;
    } else {
        *(float4*)cp = c0; *(float4*)(cp + 4) = c1;
    }
}

// output MLP: relu(h @ W1 + b1) @ W2 + b2, 4 nodes per block
__global__ void __launch_bounds__(128) k_mlp(const float* __restrict__ W1,
                                             const float* __restrict__ b1,
                                             const float* __restrict__ W2,
                                             const float* __restrict__ b2,
                                             float* __restrict__ out, int N) {
    int n0 = blockIdx.x * 4;
    int t = threadIdx.x;
    __shared__ float sh[4][HID];
    __shared__ float so[4][128];
    for (int i = t; i < 4 * HID; i += 128) {
        int u = i >> 8, c = i & (HID - 1);
        int n = n0 + u;
        sh[u][c] = (n < N) ? g_h1[(size_t)n * HID + c] : 0.f;
    }
    __syncthreads();
    float acc[4] = {b1[t], b1[t], b1[t], b1[t]};
    #pragma unroll 4
    for (int k = 0; k < HID; k++) {
        float wv = W1[k * 128 + t];
        #pragma unroll
        for (int u = 0; u < 4; u++) acc[u] += sh[u][k] * wv;
    }
    #pragma unroll
    for (int u = 0; u < 4; u++) so[u][t] = fmaxf(acc[u], 0.f);
    __syncthreads();
    if (t < 12) {
        int u = t / 3, j = t - u * 3;
        int n = n0 + u;
        if (n < N) {
            float a = b2[j];
            #pragma unroll 4
            for (int k = 0; k < 128; k++) a += so[u][k] * W2[k * 3 + j];
            out[(size_t)n * 3 + j] = a;
        }
    }
}

// ---------------- launch ----------------
extern "C" void kernel_launch(void* const* d_in, const int* in_sizes, int n_in,
                              void* d_out, int out_size) {
    const float* x     = (const float*)d_in[0];
    const int*   date  = (const int*)d_in[1];
    const int*   ei    = (const int*)d_in[2];
    const float* pW    = (const float*)d_in[3];
    const float* pb    = (const float*)d_in[4];
    const float* Wl0   = (const float*)d_in[5];
    const float* Wr0   = (const float*)d_in[6];
    const float* att0  = (const float*)d_in[7];
    const float* b0    = (const float*)d_in[8];
    const float* Wl1   = (const float*)d_in[9];
    const float* Wr1   = (const float*)d_in[10];
    const float* att1  = (const float*)d_in[11];
    const float* b1    = (const float*)d_in[12];
    // d_in[13..15] dead (rel_agg over identical copies == identity)
    const float* oW1   = (const float*)d_in[16];
    const float* ob1   = (const float*)d_in[17];
    const float* oW2   = (const float*)d_in[18];
    const float* ob2   = (const float*)d_in[19];
    float* out = (float*)d_out;

    int N = in_sizes[0] / IN_DIM;
    int E = in_sizes[2] / (R_REL * 2);

    // ---- CSR build ----
    k_zero_cnt<<<(R_REL * N + 255) / 256, 256>>>(N);
    k_hist<<<(R_REL * E + 255) / 256, 256>>>(ei, N, E);
    k_scan<<<R_REL, 1024>>>(N);
    k_scatter<<<(R_REL * E + 255) / 256, 256>>>(ei, N, E);
    k_bsum<<<1, HID>>>(b0, b1);

    // ---- PE features + h0 ----
    k_pearl<<<(N * 32 + 255) / 256, 256>>>(x, N, E);
    k_build_h0<<<N, 128>>>(x, date, pW, pb, N);

    dim3 gemm_grid((HID + 127) / 128, (N + 127) / 128, 2 * R_REL);
    int gat_grid = (N * 32 + 255) / 256;

    // ---- GNN layer 0 ----
    k_gemm<<<gemm_grid, 256>>>(Wl0, Wr0, N, IN0);
    for (int r = 0; r < R_REL; r++)
        k_gat<<<gat_grid, 256>>>(att0, r, N, E, 0, r == 0, r == R_REL - 1);

    // ---- GNN layer 1 ----
    k_gemm<<<gemm_grid, 256>>>(Wl1, Wr1, N, HID);
    for (int r = 0; r < R_REL; r++)
        k_gat<<<gat_grid, 256>>>(att1, r, N, E, 1, r == 0, r == R_REL - 1);

    // ---- output MLP ----
    k_mlp<<<(N + 3) / 4, 128>>>(oW1, ob1, oW2, ob2, out, N);
}

// round 7
// speedup vs baseline: 1.8908x; 1.0232x over previous
#include <cuda_runtime.h>
#include <cuda_bf16.h>
#include <cstdint>

// ---------------- problem constants ----------------
#define MAX_N 20000
#define MAX_E 320000
#define R_REL 5
#define IN_DIM 64
#define IN0 112          // 64 + 32 + 16
#define HID 256
#define NHEAD 4
#define NEG_SLOPE 0.2f

// ---------------- static device scratch (zero-initialized at module load) ------
__device__ float g_h0[(size_t)MAX_N * IN0];
__device__ float g_agg[(size_t)MAX_N * IN_DIM];
__device__ float g_xl[(size_t)R_REL * MAX_N * HID];
__device__ float g_xr[(size_t)R_REL * MAX_N * HID];
__device__ float g_out1[(size_t)MAX_N * HID];   // layer-0 output
__device__ float g_out2[(size_t)MAX_N * HID];   // layer-1 output
__device__ float g_bsum[2][HID];
// CSR scratch. g_cnt MUST be zero on entry: zero at module load; the tail
// kernel of every kernel_launch call re-zeroes it, so every call (correctness,
// capture, every replay) sees identical initial state.
__device__ int g_cnt[R_REL * MAX_N];
__device__ int g_cur[R_REL * MAX_N];
__device__ int g_off[R_REL * MAX_N];
__device__ int g_csr[(size_t)R_REL * MAX_E];

__device__ __forceinline__ float lrelu(float m) { return m > 0.f ? m : NEG_SLOPE * m; }

// ---------------- CSR build ----------------
__global__ void k_hist(const int* __restrict__ ei, int N, int E) {
    int i = blockIdx.x * blockDim.x + threadIdx.x;
    if (i >= R_REL * E) return;
    int r = i / E, e = i - r * E;
    int dst = ei[(size_t)(r * 2 + 1) * E + e];
    atomicAdd(&g_cnt[r * N + dst], 1);
}

// exclusive scan per relation (one 1024-thread block per relation)
__global__ void __launch_bounds__(1024) k_scan(int N) {
    int r = blockIdx.x;
    __shared__ int sh[1024];
    int t = threadIdx.x;
    int carry = 0;
    int nchunk = (N + 1023) / 1024;
    for (int c = 0; c < nchunk; c++) {
        int i = c * 1024 + t;
        int v = (i < N) ? g_cnt[r * N + i] : 0;
        sh[t] = v;
        __syncthreads();
        #pragma unroll
        for (int off = 1; off < 1024; off <<= 1) {
            int x = (t >= off) ? sh[t - off] : 0;
            __syncthreads();
            if (t >= off) sh[t] += x;
            __syncthreads();
        }
        int incl = sh[t];
        if (i < N) {
            int excl = incl - v + carry;
            g_off[r * N + i] = excl;
            g_cur[r * N + i] = excl;   // running cursor for scatter
        }
        carry += sh[1023];
        __syncthreads();
    }
}

__global__ void k_scatter(const int* __restrict__ ei, int N, int E) {
    int i = blockIdx.x * blockDim.x + threadIdx.x;
    if (i >= R_REL * E) return;
    int r = i / E, e = i - r * E;
    int src = ei[(size_t)(r * 2 + 0) * E + e];
    int dst = ei[(size_t)(r * 2 + 1) * E + e];
    int pos = atomicAdd(&g_cur[r * N + dst], 1);
    g_csr[(size_t)r * E + pos] = src;
}

// tail restore: g_cnt back to zero for the next call / graph replay
__global__ void k_zero_cnt(int N) {
    int i = blockIdx.x * blockDim.x + threadIdx.x;
    if (i < R_REL * N) g_cnt[i] = 0;
}

// ---------------- PEARL mean aggregation (warp per dst, CSR) -------------------
// Positioned as launch #4 so the harness ncu capture profiles it.
__global__ void __launch_bounds__(256) k_pearl(const float* __restrict__ x, int N, int E) {
    int w = (blockIdx.x * blockDim.x + threadIdx.x) >> 5;
    int lane = threadIdx.x & 31;
    if (w >= N) return;
    int d = w;
    float ax = 0.f, ay = 0.f;
    int deg = 0;
    #pragma unroll
    for (int r = 0; r < R_REL; r++) {
        int beg = g_off[r * N + d], num = g_cnt[r * N + d];
        deg += num;
        const int* srcs = g_csr + (size_t)r * E + beg;
        for (int base = 0; base < num; base += 32) {
            int my = (base + lane < num) ? srcs[base + lane] : 0;
            int lim = min(32, num - base);
            for (int q = 0; q < lim; q++) {
                int src = __shfl_sync(0xffffffffu, my, q);
                float2 v = *(const float2*)(x + (size_t)src * IN_DIM + lane * 2);
                ax += v.x; ay += v.y;
            }
        }
    }
    float inv = 1.f / fmaxf((float)deg, 1.f);
    *(float2*)(g_agg + (size_t)d * IN_DIM + lane * 2) = make_float2(ax * inv, ay * inv);
}

// bias sums for both layers: g_bsum[l][c] = sum_r b_l[r][c]
__global__ void k_bsum(const float* __restrict__ b0, const float* __restrict__ b1) {
    int c = threadIdx.x;
    float s0 = 0.f, s1 = 0.f;
    #pragma unroll
    for (int r = 0; r < R_REL; r++) { s0 += b0[r * HID + c]; s1 += b1[r * HID + c]; }
    g_bsum[0][c] = s0; g_bsum[1][c] = s1;
}

// build h0 = [x | tanh(mean_agg @ Wp + bp) | time_pe], 8 nodes/block, Wp in smem
__global__ void __launch_bounds__(256) k_build_h0(const float* __restrict__ x,
                                                  const int* __restrict__ date,
                                                  const float* __restrict__ Wp,
                                                  const float* __restrict__ bp, int N) {
    __shared__ float sWp[IN_DIM * 32];
    __shared__ float sam[8][IN_DIM];
    int t = threadIdx.x;
    int n0 = blockIdx.x * 8;
    for (int i = t; i < IN_DIM * 32; i += 256) sWp[i] = Wp[i];
    for (int i = t; i < 8 * IN_DIM; i += 256) {
        int u = i >> 6, k = i & 63;
        int n = n0 + u;
        sam[u][k] = (n < N) ? g_agg[(size_t)n * IN_DIM + k] : 0.f;
    }
    __syncthreads();
    int u2 = t >> 7, t1 = t & 127;
    #pragma unroll
    for (int ui = 0; ui < 4; ui++) {
        int u = ui * 2 + u2;
        int n = n0 + u;
        if (n < N) {
            float* hrow = g_h0 + (size_t)n * IN0;
            if (t1 < 64) {
                hrow[t1] = x[(size_t)n * IN_DIM + t1];
            } else if (t1 < 96) {
                int c = t1 - 64;
                float acc = bp[c];
                #pragma unroll
                for (int k = 0; k < IN_DIM; k++) acc += sam[u][k] * sWp[k * 32 + c];
                hrow[64 + c] = tanhf(acc);
            } else if (t1 < 112) {
                int j = t1 - 96;
                int jj = j & 7;
                float tt = (float)date[n] / 10000.f;
                float div = expf(-(float)(2 * jj) * (logf(10000.f) / 16.f));
                float a = tt * div;
                hrow[96 + j] = (j < 8) ? sinf(a) : cosf(a);
            }
        }
    }
}

// batched SGEMM: 128x128 tile, 256 threads, 8x8 microtile
__global__ void __launch_bounds__(256) k_gemm(const float* __restrict__ Wl,
                                              const float* __restrict__ Wr,
                                              int N, int K) {
    int z = blockIdx.z;
    const float* A = (K == IN0) ? g_h0 : g_out1;
    const float* B = (z < R_REL) ? Wl + (size_t)z * K * HID
                                 : Wr + (size_t)(z - R_REL) * K * HID;
    float* C = (z < R_REL) ? g_xl + (size_t)z * N * HID
                           : g_xr + (size_t)(z - R_REL) * N * HID;
    __shared__ float As[16][132];
    __shared__ float Bs[16][128];
    int tid = threadIdx.x;
    int row0 = blockIdx.y * 128, col0 = blockIdx.x * 128;
    int tx = tid & 15, ty = tid >> 4;
    float acc[8][8] = {};
    for (int k0 = 0; k0 < K; k0 += 16) {
        #pragma unroll
        for (int i = 0; i < 2; i++) {
            int idx = tid * 2 + i;
            int ar = idx >> 2, ac4 = (idx & 3) * 4;
            float4 av = make_float4(0.f, 0.f, 0.f, 0.f);
            int gr = row0 + ar;
            if (gr < N) av = *(const float4*)(A + (size_t)gr * K + k0 + ac4);
            As[ac4 + 0][ar] = av.x; As[ac4 + 1][ar] = av.y;
            As[ac4 + 2][ar] = av.z; As[ac4 + 3][ar] = av.w;
            int br = idx >> 5, bc = (idx & 31) * 4;
            *(float4*)&Bs[br][bc] = *(const float4*)(B + (size_t)(k0 + br) * HID + col0 + bc);
        }
        __syncthreads();
        #pragma unroll
        for (int kk = 0; kk < 16; kk++) {
            float a[8], b[8];
            *(float4*)(a)     = *(const float4*)&As[kk][ty * 8];
            *(float4*)(a + 4) = *(const float4*)&As[kk][ty * 8 + 4];
            *(float4*)(b)     = *(const float4*)&Bs[kk][tx * 8];
            *(float4*)(b + 4) = *(const float4*)&Bs[kk][tx * 8 + 4];
            #pragma unroll
            for (int i = 0; i < 8; i++)
                #pragma unroll
                for (int j = 0; j < 8; j++) acc[i][j] += a[i] * b[j];
        }
        __syncthreads();
    }
    #pragma unroll
    for (int i = 0; i < 8; i++) {
        int gr = row0 + ty * 8 + i;
        if (gr < N) {
            *(float4*)(C + (size_t)gr * HID + col0 + tx * 8) =
                make_float4(acc[i][0], acc[i][1], acc[i][2], acc[i][3]);
            *(float4*)(C + (size_t)gr * HID + col0 + tx * 8 + 4) =
                make_float4(acc[i][4], acc[i][5], acc[i][6], acc[i][7]);
        }
    }
}

// Fused GATv2 layer: warp per dst, loops over all 5 relations, accumulates the
// relation-normalized outputs + bias sum in registers, relu, single write.
// NO software pipelining (R5 showed latency is occupancy-hidden) -> low reg
// pressure, no spill.
__global__ void __launch_bounds__(256) k_gat(const float* __restrict__ att,
                                             int N, int E, int layer, int which) {
    const unsigned F = 0xffffffffu;
    int w = (blockIdx.x * blockDim.x + threadIdx.x) >> 5;
    int lane = threadIdx.x & 31;
    if (w >= N) return;
    int d = w;
    float4 A0 = *(const float4*)&g_bsum[layer][lane * 8];
    float4 A1 = *(const float4*)&g_bsum[layer][lane * 8 + 4];
    for (int r = 0; r < R_REL; r++) {
        int beg = g_off[r * N + d], num = g_cnt[r * N + d];
        const float* xlbase = g_xl + (size_t)r * N * HID;
        const float4* xr4 = (const float4*)(g_xr + ((size_t)r * N + d) * HID + lane * 8);
        float4 r0 = xr4[0], r1 = xr4[1];
        const float4* at4 = (const float4*)(att + r * HID + lane * 8);
        float4 a0 = at4[0], a1 = at4[1];
        float t0 = 0.f, t1 = 0.f, t2 = 0.f, t3 = 0.f;
        float t4 = 0.f, t5 = 0.f, t6 = 0.f, t7 = 0.f;
        float denom = 0.f;
        const int* srcs = g_csr + (size_t)r * E + beg;
        for (int base = 0; base < num; base += 32) {
            int my = (base + lane < num) ? srcs[base + lane] : 0;
            int lim = min(32, num - base);
            for (int q = 0; q < lim; q++) {
                int src = __shfl_sync(F, my, q);
                const float4* xl = (const float4*)(xlbase + (size_t)src * HID + lane * 8);
                float4 l0 = xl[0], l1 = xl[1];
                float s = lrelu(l0.x + r0.x) * a0.x + lrelu(l0.y + r0.y) * a0.y
                        + lrelu(l0.z + r0.z) * a0.z + lrelu(l0.w + r0.w) * a0.w
                        + lrelu(l1.x + r1.x) * a1.x + lrelu(l1.y + r1.y) * a1.y
                        + lrelu(l1.z + r1.z) * a1.z + lrelu(l1.w + r1.w) * a1.w;
                s += __shfl_xor_sync(F, s, 4);
                s += __shfl_xor_sync(F, s, 2);
                s += __shfl_xor_sync(F, s, 1);
                float ex = expf(s);
                denom += ex;
                t0 += ex * l0.x; t1 += ex * l0.y; t2 += ex * l0.z; t3 += ex * l0.w;
                t4 += ex * l1.x; t5 += ex * l1.y; t6 += ex * l1.z; t7 += ex * l1.w;
            }
        }
        float inv = 1.f / (denom + 1e-16f);   // num==0: t==0 -> contributes 0
        A0.x += t0 * inv; A0.y += t1 * inv; A0.z += t2 * inv; A0.w += t3 * inv;
        A1.x += t4 * inv; A1.y += t5 * inv; A1.z += t6 * inv; A1.w += t7 * inv;
    }
    A0.x = fmaxf(A0.x, 0.f); A0.y = fmaxf(A0.y, 0.f);
    A0.z = fmaxf(A0.z, 0.f); A0.w = fmaxf(A0.w, 0.f);
    A1.x = fmaxf(A1.x, 0.f); A1.y = fmaxf(A1.y, 0.f);
    A1.z = fmaxf(A1.z, 0.f); A1.w = fmaxf(A1.w, 0.f);
    float* outbuf = which ? g_out2 : g_out1;
    float* hp = outbuf + (size_t)d * HID + lane * 8;
    *(float4*)hp = A0; *(float4*)(hp + 4) = A1;
}

// output MLP: relu(h @ W1 + b1) @ W2 + b2, 16 nodes per block, 256 threads
__global__ void __launch_bounds__(256) k_mlp(const float* __restrict__ W1,
                                             const float* __restrict__ b1,
                                             const float* __restrict__ W2,
                                             const float* __restrict__ b2,
                                             float* __restrict__ out, int N) {
    __shared__ float sh[HID][17];   // [k][node], padded
    __shared__ float so[16][129];
    int t = threadIdx.x;
    int n0 = blockIdx.x * 16;
    for (int i = t; i < 16 * HID; i += 256) {
        int u = i >> 8, c = i & (HID - 1);
        int n = n0 + u;
        sh[c][u] = (n < N) ? g_out2[(size_t)n * HID + c] : 0.f;
    }
    __syncthreads();
    int ct = t & 127, ug = t >> 7;
    float acc[8];
    float bb = b1[ct];
    #pragma unroll
    for (int j = 0; j < 8; j++) acc[j] = bb;
    for (int k = 0; k < HID; k++) {
        float wv = W1[k * 128 + ct];
        #pragma unroll
        for (int j = 0; j < 8; j++) acc[j] += sh[k][ug * 8 + j] * wv;
    }
    #pragma unroll
    for (int j = 0; j < 8; j++) so[ug * 8 + j][ct] = fmaxf(acc[j], 0.f);
    __syncthreads();
    if (t < 48) {
        int u = t / 3, j = t - u * 3;
        int n = n0 + u;
        if (n < N) {
            float a = b2[j];
            #pragma unroll 4
            for (int k = 0; k < 128; k++) a += so[u][k] * W2[k * 3 + j];
            out[(size_t)n * 3 + j] = a;
        }
    }
}

// ---------------- launch ----------------
extern "C" void kernel_launch(void* const* d_in, const int* in_sizes, int n_in,
                              void* d_out, int out_size) {
    const float* x     = (const float*)d_in[0];
    const int*   date  = (const int*)d_in[1];
    const int*   ei    = (const int*)d_in[2];
    const float* pW    = (const float*)d_in[3];
    const float* pb    = (const float*)d_in[4];
    const float* Wl0   = (const float*)d_in[5];
    const float* Wr0   = (const float*)d_in[6];
    const float* att0  = (const float*)d_in[7];
    const float* b0    = (const float*)d_in[8];
    const float* Wl1   = (const float*)d_in[9];
    const float* Wr1   = (const float*)d_in[10];
    const float* att1  = (const float*)d_in[11];
    const float* b1    = (const float*)d_in[12];
    // d_in[13..15] dead (rel_agg over identical copies == identity)
    const float* oW1   = (const float*)d_in[16];
    const float* ob1   = (const float*)d_in[17];
    const float* oW2   = (const float*)d_in[18];
    const float* ob2   = (const float*)d_in[19];
    float* out = (float*)d_out;

    int N = in_sizes[0] / IN_DIM;
    int E = in_sizes[2] / (R_REL * 2);

    // ---- CSR build (g_cnt zero: module-load init + tail restore below) ----
    k_hist<<<(R_REL * E + 255) / 256, 256>>>(ei, N, E);        // launch 1
    k_scan<<<R_REL, 1024>>>(N);                                // launch 2
    k_scatter<<<(R_REL * E + 255) / 256, 256>>>(ei, N, E);     // launch 3

    // ---- PE features + h0 ----
    k_pearl<<<(N * 32 + 255) / 256, 256>>>(x, N, E);           // launch 4 (profiled)
    k_bsum<<<1, HID>>>(b0, b1);
    k_build_h0<<<(N + 7) / 8, 256>>>(x, date, pW, pb, N);

    dim3 gemm_grid((HID + 127) / 128, (N + 127) / 128, 2 * R_REL);
    int gat_grid = (N * 32 + 255) / 256;

    // ---- GNN layer 0 ----
    k_gemm<<<gemm_grid, 256>>>(Wl0, Wr0, N, IN0);
    k_gat<<<gat_grid, 256>>>(att0, N, E, 0, 0);

    // ---- GNN layer 1 ----
    k_gemm<<<gemm_grid, 256>>>(Wl1, Wr1, N, HID);
    k_gat<<<gat_grid, 256>>>(att1, N, E, 1, 1);

    // ---- output MLP ----
    k_mlp<<<(N + 15) / 16, 256>>>(oW1, ob1, oW2, ob2, out, N);

    // ---- tail: restore g_cnt for the next call / replay ----
    k_zero_cnt<<<(R_REL * N + 255) / 256, 256>>>(N);
}

// round 13
// speedup vs baseline: 2.4968x; 1.3205x over previous
#include <cuda_runtime.h>
#include <cuda_bf16.h>
#include <cstdint>

// ---------------- problem constants ----------------
#define MAX_N 20000
#define NPAD  20096          // 157 * 128 (covers 313*64 = 20032)
#define MAX_E 320000
#define R_REL 5
#define IN_DIM 64
#define IN0 112              // 64 + 32 + 16
#define HID 256
#define NEG_SLOPE 0.2f

// ---------------- static device scratch (zero-initialized at module load) ------
__device__ float g_h0[(size_t)MAX_N * IN0];
__device__ float g_agg[(size_t)MAX_N * IN_DIM];
__device__ float g_xl[(size_t)R_REL * MAX_N * HID];
__device__ float g_xr[(size_t)R_REL * MAX_N * HID];
__device__ float g_out1[(size_t)MAX_N * HID];
__device__ float g_out2[(size_t)MAX_N * HID];
__device__ float g_bsum[2][HID];
// bf16-split GEMM operands
__device__ __nv_bfloat16 g_Ah[(size_t)NPAD * 256];
__device__ __nv_bfloat16 g_Al[(size_t)NPAD * 256];
__device__ __nv_bfloat16 g_Wth[(size_t)2 * 10 * 256 * 256];  // [l][z][n][k]
__device__ __nv_bfloat16 g_Wtl[(size_t)2 * 10 * 256 * 256];
// CSR scratch; g_cnt zero at load + tail-restored every call
__device__ int g_cnt[R_REL * MAX_N];
__device__ int g_cur[R_REL * MAX_N];
__device__ int g_off[R_REL * MAX_N];
__device__ int g_csr[(size_t)R_REL * MAX_E];

__device__ __forceinline__ float lrelu(float m) { return m > 0.f ? m : NEG_SLOPE * m; }

__device__ __forceinline__ uint32_t smem_u32(const void* p) {
    uint32_t a;
    asm("{ .reg .u64 t; cvta.to.shared.u64 t, %1; cvt.u32.u64 %0, t; }" : "=r"(a) : "l"(p));
    return a;
}

// RULE (hard-learned, R6/R10/R11/R12): NEVER pass a __device__ global symbol as
// a host-side kernel argument — the host shadow address gets passed, the device
// reads host memory via ATS (no fault!), and the driver grows a 128MiB pool ->
// harness rule violation. Select device buffers via integer flags inside
// device code only.
#define LDSM_X4(r0, r1, r2, r3, addr) \
    asm volatile("ldmatrix.sync.aligned.m8n8.x4.shared.b16 {%0,%1,%2,%3}, [%4];" \
        : "=r"(r0), "=r"(r1), "=r"(r2), "=r"(r3) : "r"(addr))

#define MMA16816(c, A, B) asm volatile( \
    "mma.sync.aligned.m16n8k16.row.col.f32.bf16.bf16.f32 " \
    "{%0,%1,%2,%3}, {%4,%5,%6,%7}, {%8,%9}, {%0,%1,%2,%3};" \
    : "+f"((c)[0]), "+f"((c)[1]), "+f"((c)[2]), "+f"((c)[3]) \
    : "r"((A)[0]), "r"((A)[1]), "r"((A)[2]), "r"((A)[3]), "r"((B)[0]), "r"((B)[1]))

// ---------------- CSR build ----------------
__global__ void k_hist(const int* __restrict__ ei, int N, int E) {
    int i = blockIdx.x * blockDim.x + threadIdx.x;
    if (i >= R_REL * E) return;
    int r = i / E, e = i - r * E;
    int dst = ei[(size_t)(r * 2 + 1) * E + e];
    atomicAdd(&g_cnt[r * N + dst], 1);
}

__global__ void __launch_bounds__(1024) k_scan(int N) {
    int r = blockIdx.x;
    __shared__ int sh[1024];
    int t = threadIdx.x;
    int carry = 0;
    int nchunk = (N + 1023) / 1024;
    for (int c = 0; c < nchunk; c++) {
        int i = c * 1024 + t;
        int v = (i < N) ? g_cnt[r * N + i] : 0;
        sh[t] = v;
        __syncthreads();
        #pragma unroll
        for (int off = 1; off < 1024; off <<= 1) {
            int x = (t >= off) ? sh[t - off] : 0;
            __syncthreads();
            if (t >= off) sh[t] += x;
            __syncthreads();
        }
        int incl = sh[t];
        if (i < N) {
            int excl = incl - v + carry;
            g_off[r * N + i] = excl;
            g_cur[r * N + i] = excl;
        }
        carry += sh[1023];
        __syncthreads();
    }
}

__global__ void k_scatter(const int* __restrict__ ei, int N, int E) {
    int i = blockIdx.x * blockDim.x + threadIdx.x;
    if (i >= R_REL * E) return;
    int r = i / E, e = i - r * E;
    int src = ei[(size_t)(r * 2 + 0) * E + e];
    int dst = ei[(size_t)(r * 2 + 1) * E + e];
    int pos = atomicAdd(&g_cur[r * N + dst], 1);
    g_csr[(size_t)r * E + pos] = src;
}

__global__ void k_zero_cnt(int N) {
    int i = blockIdx.x * blockDim.x + threadIdx.x;
    if (i < R_REL * N) g_cnt[i] = 0;
}

// ---------------- PEARL mean aggregation ----------------
__global__ void __launch_bounds__(256) k_pearl(const float* __restrict__ x, int N, int E) {
    int w = (blockIdx.x * blockDim.x + threadIdx.x) >> 5;
    int lane = threadIdx.x & 31;
    if (w >= N) return;
    int d = w;
    float ax = 0.f, ay = 0.f;
    int deg = 0;
    #pragma unroll
    for (int r = 0; r < R_REL; r++) {
        int beg = g_off[r * N + d], num = g_cnt[r * N + d];
        deg += num;
        const int* srcs = g_csr + (size_t)r * E + beg;
        for (int base = 0; base < num; base += 32) {
            int my = (base + lane < num) ? srcs[base + lane] : 0;
            int lim = min(32, num - base);
            for (int q = 0; q < lim; q++) {
                int src = __shfl_sync(0xffffffffu, my, q);
                float2 v = *(const float2*)(x + (size_t)src * IN_DIM + lane * 2);
                ax += v.x; ay += v.y;
            }
        }
    }
    float inv = 1.f / fmaxf((float)deg, 1.f);
    *(float2*)(g_agg + (size_t)d * IN_DIM + lane * 2) = make_float2(ax * inv, ay * inv);
}

__global__ void k_bsum(const float* __restrict__ b0, const float* __restrict__ b1) {
    int c = threadIdx.x;
    float s0 = 0.f, s1 = 0.f;
    #pragma unroll
    for (int r = 0; r < R_REL; r++) { s0 += b0[r * HID + c]; s1 += b1[r * HID + c]; }
    g_bsum[0][c] = s0; g_bsum[1][c] = s1;
}

// build h0, 8 nodes/block
__global__ void __launch_bounds__(256) k_build_h0(const float* __restrict__ x,
                                                  const int* __restrict__ date,
                                                  const float* __restrict__ Wp,
                                                  const float* __restrict__ bp, int N) {
    __shared__ float sWp[IN_DIM * 32];
    __shared__ float sam[8][IN_DIM];
    int t = threadIdx.x;
    int n0 = blockIdx.x * 8;
    for (int i = t; i < IN_DIM * 32; i += 256) sWp[i] = Wp[i];
    for (int i = t; i < 8 * IN_DIM; i += 256) {
        int u = i >> 6, k = i & 63;
        int n = n0 + u;
        sam[u][k] = (n < N) ? g_agg[(size_t)n * IN_DIM + k] : 0.f;
    }
    __syncthreads();
    int u2 = t >> 7, t1 = t & 127;
    #pragma unroll
    for (int ui = 0; ui < 4; ui++) {
        int u = ui * 2 + u2;
        int n = n0 + u;
        if (n < N) {
            float* hrow = g_h0 + (size_t)n * IN0;
            if (t1 < 64) {
                hrow[t1] = x[(size_t)n * IN_DIM + t1];
            } else if (t1 < 96) {
                int c = t1 - 64;
                float acc = bp[c];
                #pragma unroll
                for (int k = 0; k < IN_DIM; k++) acc += sam[u][k] * sWp[k * 32 + c];
                hrow[64 + c] = tanhf(acc);
            } else if (t1 < 112) {
                int j = t1 - 96;
                int jj = j & 7;
                float tt = (float)date[n] / 10000.f;
                float div = expf(-(float)(2 * jj) * (logf(10000.f) / 16.f));
                float a = tt * div;
                hrow[96 + j] = (j < 8) ? sinf(a) : cosf(a);
            }
        }
    }
}

// ---------------- bf16 split conversions ----------------
// which=0 -> src g_h0 (K=112), which=1 -> src g_out1 (K=256). Selector resolved
// IN DEVICE CODE (see RULE above).
__global__ void __launch_bounds__(256) k_cvtA(int which, int srcK, int N) {
    const float* src = which ? g_out1 : g_h0;
    int row = blockIdx.x;
    int k = threadIdx.x;
    float v = (row < N && k < srcK) ? src[(size_t)row * srcK + k] : 0.f;
    __nv_bfloat16 h = __float2bfloat16(v);
    __nv_bfloat16 l = __float2bfloat16(v - __bfloat162float(h));
    g_Ah[(size_t)row * 256 + k] = h;
    g_Al[(size_t)row * 256 + k] = l;
}

__global__ void __launch_bounds__(256) k_cvtW(const float* __restrict__ Wl0,
                                              const float* __restrict__ Wr0,
                                              const float* __restrict__ Wl1,
                                              const float* __restrict__ Wr1) {
    int n = blockIdx.x;
    int z = blockIdx.y;
    int l = blockIdx.z;
    int k = threadIdx.x;
    int srcK = (l == 0) ? IN0 : HID;
    const float* W = (l == 0) ? ((z < 5) ? Wl0 : Wr0) : ((z < 5) ? Wl1 : Wr1);
    int zz = z % 5;
    float v = (k < srcK) ? W[((size_t)zz * srcK + k) * HID + n] : 0.f;
    __nv_bfloat16 h = __float2bfloat16(v);
    __nv_bfloat16 lo = __float2bfloat16(v - __bfloat162float(h));
    size_t di = ((size_t)(l * 10 + z) * 256 + n) * 256 + k;
    g_Wth[di] = h;
    g_Wtl[di] = lo;
}

// ---------------- bf16-split GEMM via mma.sync --------------------------------
// CTA: 128 threads (4 warps), tile 64(M) x 64(N); warp tile 32x32.
// D = Ah*Bh + Ah*Bl + Al*Bh, fp32 accum (dropped Al*Bl <= 2^-16 rel).
__global__ void __launch_bounds__(128) k_mma(int Nn, int layer, int K) {
    __shared__ __nv_bfloat16 sAh[64 * 40];
    __shared__ __nv_bfloat16 sAl[64 * 40];
    __shared__ __nv_bfloat16 sBh[64 * 40];
    __shared__ __nv_bfloat16 sBl[64 * 40];
    int tid = threadIdx.x;
    int lane = tid & 31, wid = tid >> 5;
    int wm = wid & 1, wn = wid >> 1;               // warp tile: (wm*32, wn*32)
    int row0 = blockIdx.x * 64;
    int nb = blockIdx.y * 64;
    int z = blockIdx.z;

    uint32_t uAh = smem_u32(sAh), uAl = smem_u32(sAl);
    uint32_t uBh = smem_u32(sBh), uBl = smem_u32(sBl);

    const uint4* Ah4 = (const uint4*)g_Ah;
    const uint4* Al4 = (const uint4*)g_Al;
    const uint4* Wh4 = (const uint4*)g_Wth;
    const uint4* Wl4 = (const uint4*)g_Wtl;
    size_t wrow0 = (size_t)(layer * 10 + z) * 256 + nb;

    // ldmatrix lane base offsets (80B padded rows)
    int lr = lane & 7, g = lane >> 3;
    // A atoms: (m0,k0),(m8,k0),(m0,k8),(m8,k8)
    uint32_t offA = (uint32_t)((wm * 32 + (g & 1) * 8 + lr) * 80 + ((g >> 1) * 8) * 2);
    // B atoms: (n0,k0),(n0,k8),(n8,k0),(n8,k8)
    uint32_t offB = (uint32_t)((wn * 32 + (g >> 1) * 8 + lr) * 80 + ((g & 1) * 8) * 2);

    float acc[2][4][4] = {};
    for (int k0 = 0; k0 < K; k0 += 32) {
        // load chunk: A 64x32, B 64x32, hi+lo; each thread 2 uint4 per buffer
        #pragma unroll
        for (int it = 0; it < 2; it++) {
            int idx = tid + it * 128;              // 0..255
            int row = idx >> 2, q = idx & 3;
            size_t ga = (size_t)(row0 + row) * 32 + (k0 >> 3) + q;
            size_t gb = (wrow0 + row) * 32 + (k0 >> 3) + q;
            *(uint4*)((char*)sAh + row * 80 + q * 16) = Ah4[ga];
            *(uint4*)((char*)sAl + row * 80 + q * 16) = Al4[ga];
            *(uint4*)((char*)sBh + row * 80 + q * 16) = Wh4[gb];
            *(uint4*)((char*)sBl + row * 80 + q * 16) = Wl4[gb];
        }
        __syncthreads();
        #pragma unroll
        for (int ks = 0; ks < 32; ks += 16) {
            uint32_t kb = (uint32_t)(ks * 2);
            uint32_t a[2][4], bh[4][2], bl[4][2];
            #pragma unroll
            for (int j8 = 0; j8 < 2; j8++) {
                LDSM_X4(bh[2 * j8][0], bh[2 * j8][1], bh[2 * j8 + 1][0], bh[2 * j8 + 1][1],
                        uBh + offB + kb + (uint32_t)(j8 * 16 * 80));
                LDSM_X4(bl[2 * j8][0], bl[2 * j8][1], bl[2 * j8 + 1][0], bl[2 * j8 + 1][1],
                        uBl + offB + kb + (uint32_t)(j8 * 16 * 80));
            }
            #pragma unroll
            for (int i = 0; i < 2; i++)
                LDSM_X4(a[i][0], a[i][1], a[i][2], a[i][3],
                        uAh + offA + kb + (uint32_t)(i * 16 * 80));
            #pragma unroll
            for (int i = 0; i < 2; i++)
                #pragma unroll
                for (int j = 0; j < 4; j++) { MMA16816(acc[i][j], a[i], bh[j]); }
            #pragma unroll
            for (int i = 0; i < 2; i++)
                #pragma unroll
                for (int j = 0; j < 4; j++) { MMA16816(acc[i][j], a[i], bl[j]); }
            #pragma unroll
            for (int i = 0; i < 2; i++)
                LDSM_X4(a[i][0], a[i][1], a[i][2], a[i][3],
                        uAl + offA + kb + (uint32_t)(i * 16 * 80));
            #pragma unroll
            for (int i = 0; i < 2; i++)
                #pragma unroll
                for (int j = 0; j < 4; j++) { MMA16816(acc[i][j], a[i], bh[j]); }
        }
        __syncthreads();
    }
    // store: C frag (row = lane>>2, cols 2*(lane&3); +8 rows for c2,c3)
    float* base = ((z < 5) ? g_xl : g_xr) + (size_t)(z % 5) * Nn * HID;
    #pragma unroll
    for (int i = 0; i < 2; i++) {
        #pragma unroll
        for (int j = 0; j < 4; j++) {
            int m = row0 + wm * 32 + i * 16 + (lane >> 2);
            int nn = nb + wn * 32 + j * 8 + (lane & 3) * 2;
            if (m < Nn)
                *(float2*)&base[(size_t)m * HID + nn] = make_float2(acc[i][j][0], acc[i][j][1]);
            if (m + 8 < Nn)
                *(float2*)&base[(size_t)(m + 8) * HID + nn] = make_float2(acc[i][j][2], acc[i][j][3]);
        }
    }
}

// ---------------- fused GATv2 layer ----------------
__global__ void __launch_bounds__(256) k_gat(const float* __restrict__ att,
                                             int N, int E, int layer, int which) {
    const unsigned F = 0xffffffffu;
    int w = (blockIdx.x * blockDim.x + threadIdx.x) >> 5;
    int lane = threadIdx.x & 31;
    if (w >= N) return;
    int d = w;
    float4 A0 = *(const float4*)&g_bsum[layer][lane * 8];
    float4 A1 = *(const float4*)&g_bsum[layer][lane * 8 + 4];
    for (int r = 0; r < R_REL; r++) {
        int beg = g_off[r * N + d], num = g_cnt[r * N + d];
        const float* xlbase = g_xl + (size_t)r * N * HID;
        const float4* xr4 = (const float4*)(g_xr + ((size_t)r * N + d) * HID + lane * 8);
        float4 r0 = xr4[0], r1 = xr4[1];
        const float4* at4 = (const float4*)(att + r * HID + lane * 8);
        float4 a0 = at4[0], a1 = at4[1];
        float t0 = 0.f, t1 = 0.f, t2 = 0.f, t3 = 0.f;
        float t4 = 0.f, t5 = 0.f, t6 = 0.f, t7 = 0.f;
        float denom = 0.f;
        const int* srcs = g_csr + (size_t)r * E + beg;
        for (int base = 0; base < num; base += 32) {
            int my = (base + lane < num) ? srcs[base + lane] : 0;
            int lim = min(32, num - base);
            for (int q = 0; q < lim; q++) {
                int src = __shfl_sync(F, my, q);
                const float4* xl = (const float4*)(xlbase + (size_t)src * HID + lane * 8);
                float4 l0 = xl[0], l1 = xl[1];
                float s = lrelu(l0.x + r0.x) * a0.x + lrelu(l0.y + r0.y) * a0.y
                        + lrelu(l0.z + r0.z) * a0.z + lrelu(l0.w + r0.w) * a0.w
                        + lrelu(l1.x + r1.x) * a1.x + lrelu(l1.y + r1.y) * a1.y
                        + lrelu(l1.z + r1.z) * a1.z + lrelu(l1.w + r1.w) * a1.w;
                s += __shfl_xor_sync(F, s, 4);
                s += __shfl_xor_sync(F, s, 2);
                s += __shfl_xor_sync(F, s, 1);
                float ex = expf(s);
                denom += ex;
                t0 += ex * l0.x; t1 += ex * l0.y; t2 += ex * l0.z; t3 += ex * l0.w;
                t4 += ex * l1.x; t5 += ex * l1.y; t6 += ex * l1.z; t7 += ex * l1.w;
            }
        }
        float inv = 1.f / (denom + 1e-16f);
        A0.x += t0 * inv; A0.y += t1 * inv; A0.z += t2 * inv; A0.w += t3 * inv;
        A1.x += t4 * inv; A1.y += t5 * inv; A1.z += t6 * inv; A1.w += t7 * inv;
    }
    A0.x = fmaxf(A0.x, 0.f); A0.y = fmaxf(A0.y, 0.f);
    A0.z = fmaxf(A0.z, 0.f); A0.w = fmaxf(A0.w, 0.f);
    A1.x = fmaxf(A1.x, 0.f); A1.y = fmaxf(A1.y, 0.f);
    A1.z = fmaxf(A1.z, 0.f); A1.w = fmaxf(A1.w, 0.f);
    float* outbuf = which ? g_out2 : g_out1;
    float* hp = outbuf + (size_t)d * HID + lane * 8;
    *(float4*)hp = A0; *(float4*)(hp + 4) = A1;
}

// output MLP
__global__ void __launch_bounds__(256) k_mlp(const float* __restrict__ W1,
                                             const float* __restrict__ b1,
                                             const float* __restrict__ W2,
                                             const float* __restrict__ b2,
                                             float* __restrict__ out, int N) {
    __shared__ float sh[HID][17];
    __shared__ float so[16][129];
    int t = threadIdx.x;
    int n0 = blockIdx.x * 16;
    for (int i = t; i < 16 * HID; i += 256) {
        int u = i >> 8, c = i & (HID - 1);
        int n = n0 + u;
        sh[c][u] = (n < N) ? g_out2[(size_t)n * HID + c] : 0.f;
    }
    __syncthreads();
    int ct = t & 127, ug = t >> 7;
    float acc[8];
    float bb = b1[ct];
    #pragma unroll
    for (int j = 0; j < 8; j++) acc[j] = bb;
    for (int k = 0; k < HID; k++) {
        float wv = W1[k * 128 + ct];
        #pragma unroll
        for (int j = 0; j < 8; j++) acc[j] += sh[k][ug * 8 + j] * wv;
    }
    #pragma unroll
    for (int j = 0; j < 8; j++) so[ug * 8 + j][ct] = fmaxf(acc[j], 0.f);
    __syncthreads();
    if (t < 48) {
        int u = t / 3, j = t - u * 3;
        int n = n0 + u;
        if (n < N) {
            float a = b2[j];
            #pragma unroll 4
            for (int k = 0; k < 128; k++) a += so[u][k] * W2[k * 3 + j];
            out[(size_t)n * 3 + j] = a;
        }
    }
}

// ---------------- launch ----------------
extern "C" void kernel_launch(void* const* d_in, const int* in_sizes, int n_in,
                              void* d_out, int out_size) {
    const float* x     = (const float*)d_in[0];
    const int*   date  = (const int*)d_in[1];
    const int*   ei    = (const int*)d_in[2];
    const float* pW    = (const float*)d_in[3];
    const float* pb    = (const float*)d_in[4];
    const float* Wl0   = (const float*)d_in[5];
    const float* Wr0   = (const float*)d_in[6];
    const float* att0  = (const float*)d_in[7];
    const float* b0    = (const float*)d_in[8];
    const float* Wl1   = (const float*)d_in[9];
    const float* Wr1   = (const float*)d_in[10];
    const float* att1  = (const float*)d_in[11];
    const float* b1    = (const float*)d_in[12];
    const float* oW1   = (const float*)d_in[16];
    const float* ob1   = (const float*)d_in[17];
    const float* oW2   = (const float*)d_in[18];
    const float* ob2   = (const float*)d_in[19];
    float* out = (float*)d_out;

    int N = in_sizes[0] / IN_DIM;
    int E = in_sizes[2] / (R_REL * 2);

    // ---- CSR build ----
    k_hist<<<(R_REL * E + 255) / 256, 256>>>(ei, N, E);
    k_scan<<<R_REL, 1024>>>(N);
    k_scatter<<<(R_REL * E + 255) / 256, 256>>>(ei, N, E);

    // ---- PE + h0 ----
    k_pearl<<<(N * 32 + 255) / 256, 256>>>(x, N, E);           // profiled slot
    k_bsum<<<1, HID>>>(b0, b1);
    k_build_h0<<<(N + 7) / 8, 256>>>(x, date, pW, pb, N);

    // ---- weight conversion ----
    dim3 wgrid(256, 10, 2);
    k_cvtW<<<wgrid, 256>>>(Wl0, Wr0, Wl1, Wr1);

    int mtiles = (N + 63) / 64;
    dim3 mma_grid(mtiles, 4, 10);
    int gat_grid = (N * 32 + 255) / 256;

    // ---- GNN layer 0 (K padded 112 -> 128) ----
    k_cvtA<<<NPAD, 256>>>(0, IN0, N);
    k_mma<<<mma_grid, 128>>>(N, 0, 128);
    k_gat<<<gat_grid, 256>>>(att0, N, E, 0, 0);

    // ---- GNN layer 1 (K = 256) ----
    k_cvtA<<<NPAD, 256>>>(1, HID, N);
    k_mma<<<mma_grid, 128>>>(N, 1, 256);
    k_gat<<<gat_grid, 256>>>(att1, N, E, 1, 1);

    // ---- output MLP ----
    k_mlp<<<(N + 15) / 16, 256>>>(oW1, ob1, oW2, ob2, out, N);

    // ---- tail: restore g_cnt ----
    k_zero_cnt<<<(R_REL * N + 255) / 256, 256>>>(N);
}